// round 14
// baseline (speedup 1.0000x reference)
#include <cuda_runtime.h>
#include <cuda_fp16.h>
#include <cstdint>

// ============================================================================
// 2-layer LSTM (B=256, T=256, IN=256, U=512) + Dense(1).
// R13 = R12 (6686us: x@W0 precomputed) + two L1/barrier cuts, mm loop intact:
//  - A staging via cp.async double-buffer (kills the LDG->reg leg: -16KB/chunk
//    of L1 wavefronts; ncu shows L1=55% vs tensor=34% -> L1-bound).
//  - Grid barrier split into 4 independent mb-group barriers (32 CTAs each);
//    h exchange is provably mb-local.
// 128 persistent CTAs (4 mb x 32 ub), CTA = 64 batch rows x 16 units.
// fp16 split-2 mma.sync.m16n8k16, fp32 accum (fp32-grade accuracy).
// ============================================================================

#define TSEQ 256
#define NB   256
#define DIN  256
#define NU   512
#define NCTA 128
#define NTHR 256

// A smem geometry (words = uint32 = 2 halves), KC=64, DOUBLE buffered
#define AROWW 36                    // row stride in words (32 + 4 pad)
#define PLANE (64 * AROWW)          // 2304 words per plane
#define AWORDS (2 * PLANE)          // hi+lo: 4608 words per buffer
#define ABYTES (AWORDS * 4)         // 18432 B per buffer
// B smem: double-buffered 16KB chunks (4 kt x 8 n8 x 32 lanes x 16B)
#define BOFF_B (2 * ABYTES)         // byte offset of B region (36864)
#define BCHUNKB 16384               // bytes per B chunk
#define SMEM_BYTES (BOFF_B + 2 * BCHUNKB)   // 69632 B

// ---- device state ----
__device__ __align__(16) __half g_xh[NB * TSEQ * DIN];
__device__ __align__(16) __half g_xl[NB * TSEQ * DIN];
__device__ __align__(16) __half g_h0h[2][NB][NU];
__device__ __align__(16) __half g_h0l[2][NB][NU];
__device__ __align__(16) __half g_h1h[2][NB][NU];
__device__ __align__(16) __half g_h1l[2][NB][NU];
__device__ unsigned g_bar[1024];    // [mb][t] = [4][256]

// precomputed x@W0, per-thread fragment layout: [t*128+tile][tid][16] f32
__device__ __align__(16) float g_z0x[(size_t)TSEQ * 128 * NTHR * 16];

// packed weight fragments: [ub][kt][n8][lane] -> 16B {b0h,b1h,b0l,b1l}
__device__ __align__(16) uint4 g_W0pk[32 * 16 * 8 * 32];
__device__ __align__(16) uint4 g_U0pk[32 * 32 * 8 * 32];
__device__ __align__(16) uint4 g_W1pk[32 * 32 * 8 * 32];
__device__ __align__(16) uint4 g_U1pk[32 * 32 * 8 * 32];

__device__ __forceinline__ float sigf(float x) { return 1.0f / (1.0f + __expf(-x)); }
__device__ __forceinline__ float tanhfast(float x) { return 2.0f / (1.0f + __expf(-2.0f * x)) - 1.0f; }

#define MMA16816(d, a0, a1, a2, a3, bb0, bb1)                                   \
    asm volatile("mma.sync.aligned.m16n8k16.row.col.f32.f16.f16.f32 "           \
        "{%0,%1,%2,%3}, {%4,%5,%6,%7}, {%8,%9}, {%0,%1,%2,%3};"                 \
        : "+f"((d)[0]), "+f"((d)[1]), "+f"((d)[2]), "+f"((d)[3])                \
        : "r"(a0), "r"(a1), "r"(a2), "r"(a3), "r"(bb0), "r"(bb1))

#define CP16(dst, src) asm volatile("cp.async.cg.shared.global [%0], [%1], 16;" \
        :: "r"(dst), "l"(src))
#define CP_COMMIT()    asm volatile("cp.async.commit_group;" ::: "memory")
#define CP_WAIT(n)     asm volatile("cp.async.wait_group %0;" :: "n"(n) : "memory")

__device__ __forceinline__ uint32_t smem_u32(const void* p) {
    uint32_t a;
    asm("{ .reg .u64 t; cvta.to.shared.u64 t, %1; cvt.u32.u64 %0, t; }" : "=r"(a) : "l"(p));
    return a;
}

// ---------------------------------------------------------------------------
// prep kernels (run every launch; deterministic)
// ---------------------------------------------------------------------------
__global__ void split_x_kernel(const float* __restrict__ x) {
    int i = blockIdx.x * blockDim.x + threadIdx.x;      // 65536 x 256 = 16.7M
    float v = x[i];
    __half hi = __float2half(v);
    g_xh[i] = hi;
    g_xl[i] = __float2half(v - __half2float(hi));
    if (i < 1024) g_bar[i] = 0u;
    if (i < 262144) {
        ((__half*)g_h0h)[i] = __ushort_as_half(0);
        ((__half*)g_h0l)[i] = __ushort_as_half(0);
        ((__half*)g_h1h)[i] = __ushort_as_half(0);
        ((__half*)g_h1l)[i] = __ushort_as_half(0);
    }
}

__device__ __forceinline__ uint32_t pack_hl(float v0, float v1, int lo) {
    __half h0 = __float2half(v0), h1 = __float2half(v1);
    if (lo) {
        h0 = __float2half(v0 - __half2float(h0));
        h1 = __float2half(v1 - __half2float(h1));
    }
    __half2 p = __halves2half2(h0, h1);
    return *(uint32_t*)&p;
}

__global__ void pack_w_kernel(const float* __restrict__ W0, const float* __restrict__ U0,
                              const float* __restrict__ W1, const float* __restrict__ U1) {
    int id = blockIdx.x * blockDim.x + threadIdx.x;     // 3584 x 256 = 917504
    int lane = id & 31;
    int n8   = (id >> 5) & 7;
    int rest = id >> 8;
    int ktg  = rest % 112;
    int ub   = rest / 112;

    const float* M; uint4* dst; int kt;
    if      (ktg < 16) { M = W0; kt = ktg;      dst = g_W0pk + (((ub * 16 + kt) * 8 + n8) * 32 + lane); }
    else if (ktg < 48) { M = U0; kt = ktg - 16; dst = g_U0pk + (((ub * 32 + kt) * 8 + n8) * 32 + lane); }
    else if (ktg < 80) { M = W1; kt = ktg - 48; dst = g_W1pk + (((ub * 32 + kt) * 8 + n8) * 32 + lane); }
    else               { M = U1; kt = ktg - 80; dst = g_U1pk + (((ub * 32 + kt) * 8 + n8) * 32 + lane); }

    int n = n8 * 8 + (lane >> 2);        // local col 0..63, n = f*4 + g
    int f = n >> 2, g = n & 3;
    int col = g * NU + ub * 16 + f;
    int k0 = kt * 16 + (lane & 3) * 2;

    float v00 = M[(size_t)(k0 + 0) * 2048 + col];
    float v01 = M[(size_t)(k0 + 1) * 2048 + col];
    float v10 = M[(size_t)(k0 + 8) * 2048 + col];
    float v11 = M[(size_t)(k0 + 9) * 2048 + col];

    uint4 o;
    o.x = pack_hl(v00, v01, 0);
    o.y = pack_hl(v10, v11, 0);
    o.z = pack_hl(v00, v01, 1);
    o.w = pack_hl(v10, v11, 1);
    *dst = o;
}

// ---------------------------------------------------------------------------
// mb-group barrier: 32 CTAs sharing the same mb (h exchange is mb-local).
__device__ __forceinline__ void gbar(int mb, int slot) {
    __syncthreads();
    if (threadIdx.x == 0) {
        __threadfence();
        unsigned* b = &g_bar[mb * 256 + slot];
        unsigned arr = atomicAdd(b, 1u) + 1u;
        if (arr < 32u) {
            while (*((volatile unsigned*)b) < 32u) __nanosleep(64);
        }
        __threadfence();
    }
    __syncthreads();
}

// issue one K-chunk: A (64 rows x 64 k, hi+lo) and B (4-kt fragment block)
// both via cp.async into double-buffered smem; ONE commit group.
__device__ __forceinline__ void issue_chunk(
    uint32_t sbase, int c, int splitc,
    const __half* a1h, const __half* a1l, int str1,
    const __half* a2h, const __half* a2l,
    const uint4* pkA, int ktA, const uint4* pkB,
    int m0, int ub)
{
    int tid = threadIdx.x;
    const __half *hi, *lo; int stride, k0;
    if (c < splitc) { hi = a1h; lo = a1l; stride = str1; k0 = c * 64; }
    else            { hi = a2h; lo = a2l; stride = NU;   k0 = (c - splitc) * 64; }

    uint32_t abase = sbase + (uint32_t)(c & 1) * ABYTES;
#pragma unroll
    for (int i = 0; i < 4; i++) {
        int idx = i * NTHR + tid;
        int pl = idx >> 9, v = idx & 511;
        int row = v >> 3, q = v & 7;
        const __half* src = (pl ? lo : hi) + (size_t)(m0 + row) * stride + k0 + q * 8;
        CP16(abase + (uint32_t)(pl * PLANE + row * AROWW + q * 4) * 4, src);
    }
    const uint4* bsrc = (c < splitc)
        ? pkA + (size_t)(ub * ktA + c * 4) * 256
        : pkB + (size_t)(ub * 32 + (c - splitc) * 4) * 256;
    uint32_t bbase = sbase + BOFF_B + (uint32_t)(c & 1) * BCHUNKB;
#pragma unroll
    for (int i = 0; i < 4; i++) {
        int idx = i * NTHR + tid;
        CP16(bbase + idx * 16, (const void*)(bsrc + idx));
    }
    CP_COMMIT();
}

// one layer: nchunks K-chunks of 64, A+B both cp.async double-buffered,
// 2 commit groups in flight. acc[4][4] per warp (m16 x n32).
// zinit: optional per-thread fragment-layout initial accumulator (else 0).
__device__ __forceinline__ void run_layer(
    uint32_t* sbuf, uint32_t sbase,
    int nchunks, int splitc,
    const __half* a1h, const __half* a1l, int str1,
    const __half* a2h, const __half* a2l,
    const uint4* pkA, int ktA, const uint4* pkB,
    int m0, int ub, float acc[4][4], const float4* zinit)
{
    int tid = threadIdx.x, lane = tid & 31, w = tid >> 5;
    int warpM = w & 3, nh = w >> 2;

    if (zinit) {
#pragma unroll
        for (int nt = 0; nt < 4; nt++) {
            float4 v = zinit[nt];
            acc[nt][0] = v.x; acc[nt][1] = v.y; acc[nt][2] = v.z; acc[nt][3] = v.w;
        }
    } else {
#pragma unroll
        for (int nt = 0; nt < 4; nt++)
#pragma unroll
            for (int r = 0; r < 4; r++) acc[nt][r] = 0.f;
    }

    issue_chunk(sbase, 0, splitc, a1h, a1l, str1, a2h, a2l, pkA, ktA, pkB, m0, ub);
    if (nchunks > 1)
        issue_chunk(sbase, 1, splitc, a1h, a1l, str1, a2h, a2l, pkA, ktA, pkB, m0, ub);

#pragma unroll 1
    for (int c = 0; c < nchunks; c++) {
        if (c + 1 < nchunks) CP_WAIT(1); else CP_WAIT(0);
        __syncthreads();                 // group c data visible to all warps

        uint32_t* sAh = sbuf + (size_t)(c & 1) * AWORDS;
        uint32_t* sAl = sAh + PLANE;
        const uint4* sBv = (const uint4*)((char*)sbuf + BOFF_B + (size_t)(c & 1) * BCHUNKB);
#pragma unroll
        for (int j = 0; j < 4; j++) {
            const uint4* bq = sBv + ((j * 8 + nh * 4) * 32 + lane);
            uint4 f0 = bq[0];
            uint4 f1 = bq[32];
            uint4 f2 = bq[64];
            uint4 f3 = bq[96];

            int ab = (warpM * 16 + (lane >> 2)) * AROWW + j * 8 + (lane & 3);
            uint32_t ah0 = sAh[ab],       ah1 = sAh[ab + 8 * AROWW];
            uint32_t ah2 = sAh[ab + 4],   ah3 = sAh[ab + 8 * AROWW + 4];
            uint32_t al0 = sAl[ab],       al1 = sAl[ab + 8 * AROWW];
            uint32_t al2 = sAl[ab + 4],   al3 = sAl[ab + 8 * AROWW + 4];

            MMA16816(acc[0], ah0, ah1, ah2, ah3, f0.x, f0.y);
            MMA16816(acc[1], ah0, ah1, ah2, ah3, f1.x, f1.y);
            MMA16816(acc[2], ah0, ah1, ah2, ah3, f2.x, f2.y);
            MMA16816(acc[3], ah0, ah1, ah2, ah3, f3.x, f3.y);
            MMA16816(acc[0], ah0, ah1, ah2, ah3, f0.z, f0.w);
            MMA16816(acc[1], ah0, ah1, ah2, ah3, f1.z, f1.w);
            MMA16816(acc[2], ah0, ah1, ah2, ah3, f2.z, f2.w);
            MMA16816(acc[3], ah0, ah1, ah2, ah3, f3.z, f3.w);
            MMA16816(acc[0], al0, al1, al2, al3, f0.x, f0.y);
            MMA16816(acc[1], al0, al1, al2, al3, f1.x, f1.y);
            MMA16816(acc[2], al0, al1, al2, al3, f2.x, f2.y);
            MMA16816(acc[3], al0, al1, al2, al3, f3.x, f3.y);
        }
        __syncthreads();                 // all warps done with buffer c&1
        if (c + 2 < nchunks)
            issue_chunk(sbase, c + 2, splitc, a1h, a1l, str1, a2h, a2l,
                        pkA, ktA, pkB, m0, ub);
    }
}

// ---------------------------------------------------------------------------
// precompute z0x = x @ W0 (no bias), all timesteps in parallel.
__global__ void __launch_bounds__(NTHR, 1) precomp_kernel() {
    extern __shared__ __align__(16) uint32_t sbuf[];
    int bid = blockIdx.x;
    int t = bid >> 7;
    int bx = bid & 127;
    int ub = bx & 31, mb = bx >> 5;
    int m0 = mb * 64;
    uint32_t sbase = smem_u32(sbuf);

    float acc[4][4];
    run_layer(sbuf, sbase, 4, 4,
              g_xh + t * DIN, g_xl + t * DIN, TSEQ * DIN,
              (const __half*)0, (const __half*)0,
              g_W0pk, 16, g_W0pk,
              m0, ub, acc, (const float4*)0);

    float4* dst = (float4*)&g_z0x[(((size_t)bid) * NTHR + threadIdx.x) * 16];
#pragma unroll
    for (int nt = 0; nt < 4; nt++)
        dst[nt] = make_float4(acc[nt][0], acc[nt][1], acc[nt][2], acc[nt][3]);
}

// epilogue: gate exchange via shfl_xor(1), cell update, write h hi/lo planes.
__device__ __forceinline__ void epilogue(float acc[4][4], float cst[4],
                                         const float* sb,
                                         __half* dsth, __half* dstl,
                                         int m0, int u0)
{
    int tid = threadIdx.x, lane = tid & 31, w = tid >> 5;
    int warpM = w & 3, nh = w >> 2;
    int gp = lane & 1;
    int rlow = m0 + warpM * 16 + (lane >> 2);
#pragma unroll
    for (int nt = 0; nt < 4; nt++) {
        float c0 = acc[nt][0], c1 = acc[nt][1], c2 = acc[nt][2], c3 = acc[nt][3];
        float e0 = __shfl_xor_sync(0xffffffffu, c0, 1);
        float e1 = __shfl_xor_sync(0xffffffffu, c1, 1);
        float e2 = __shfl_xor_sync(0xffffffffu, c2, 1);
        float e3 = __shfl_xor_sync(0xffffffffu, c3, 1);
        float zi, zf, zg, zo; int row;
        if (!gp) { zi = c0; zf = c1; zg = e0; zo = e1; row = rlow; }
        else     { zi = e2; zf = e3; zg = c2; zo = c3; row = rlow + 8; }
        int ul = nh * 8 + nt * 2 + ((lane >> 1) & 1);
        zi += sb[ul * 4 + 0]; zf += sb[ul * 4 + 1];
        zg += sb[ul * 4 + 2]; zo += sb[ul * 4 + 3];
        float cn = sigf(zf) * cst[nt] + sigf(zi) * tanhfast(zg);
        cst[nt] = cn;
        float h = sigf(zo) * tanhfast(cn);
        __half hh = __float2half(h);
        __half hl = __float2half(h - __half2float(hh));
        dsth[(size_t)row * NU + u0 + ul] = hh;
        dstl[(size_t)row * NU + u0 + ul] = hl;
    }
}

// ---------------------------------------------------------------------------
__global__ void __launch_bounds__(NTHR, 1) lstm_kernel(
    const float* __restrict__ b0, const float* __restrict__ b1)
{
    extern __shared__ __align__(16) uint32_t sbuf[];   // A 2x18432 | B 2x16KB
    __shared__ float sb0[64], sb1[64];

    int tid = threadIdx.x;
    int bx = blockIdx.x;
    int ub = bx & 31, mb = bx >> 5;
    int u0 = ub * 16, m0 = mb * 64;
    uint32_t sbase = smem_u32(sbuf);

    if (tid < 64) {
        int f = tid >> 2, g = tid & 3;
        sb0[tid] = b0[g * NU + u0 + f];
        sb1[tid] = b1[g * NU + u0 + f];
    }
    __syncthreads();

    float cst0[4] = {0.f, 0.f, 0.f, 0.f};
    float cst1[4] = {0.f, 0.f, 0.f, 0.f};
    float acc[4][4];

#pragma unroll 1
    for (int t = 0; t < TSEQ; t++) {
        int p = t & 1;
        const __half* h0ch = &g_h0h[p][0][0];     const __half* h0cl = &g_h0l[p][0][0];
        __half*       h0nh = &g_h0h[p ^ 1][0][0]; __half*       h0nl = &g_h0l[p ^ 1][0][0];
        const __half* h1ch = &g_h1h[p][0][0];     const __half* h1cl = &g_h1l[p][0][0];
        __half*       h1nh = &g_h1h[p ^ 1][0][0]; __half*       h1nl = &g_h1l[p ^ 1][0][0];

        // layer 0: acc init = z0x(t) fragments; A = h0c (8 chunks), B = U0pk
        const float4* zi = (const float4*)
            &g_z0x[(((size_t)(t * 128 + bx)) * NTHR + tid) * 16];
        run_layer(sbuf, sbase, 8, 8,
                  h0ch, h0cl, NU,
                  (const __half*)0, (const __half*)0,
                  g_U0pk, 32, g_U0pk,
                  m0, ub, acc, zi);
        epilogue(acc, cst0, sb0, h0nh, h0nl, m0, u0);
        gbar(mb, t);    // mb-group barrier (32 CTAs): h exchange is mb-local

        // layer 1: A = [h0n (8 chunks) | h1c (8 chunks)], B = [W1pk ; U1pk]
        run_layer(sbuf, sbase, 16, 8,
                  h0nh, h0nl, NU,
                  h1ch, h1cl,
                  g_W1pk, 32, g_U1pk,
                  m0, ub, acc, (const float4*)0);
        epilogue(acc, cst1, sb1, h1nh, h1nl, m0, u0);
    }
}

// Final head: out[b] = h1_final[b,:] @ Wfc + bfc. Final h1 is in plane buffer 0.
__global__ void out_kernel(const float* __restrict__ Wfc,
                           const float* __restrict__ bfc,
                           float* __restrict__ out)
{
    int warp = threadIdx.x >> 5, lane = threadIdx.x & 31;
    int wglob = blockIdx.x * 8 + warp;
#pragma unroll
    for (int i = 0; i < 4; i++) {
        int b = wglob * 4 + i;
        float s = 0.f;
        for (int u = lane; u < NU; u += 32) {
            float h = __half2float(g_h1h[0][b][u]) + __half2float(g_h1l[0][b][u]);
            s += h * Wfc[u];
        }
#pragma unroll
        for (int off = 16; off; off >>= 1) s += __shfl_down_sync(0xffffffffu, s, off);
        if (lane == 0) out[b] = s + bfc[0];
    }
}

extern "C" void kernel_launch(void* const* d_in, const int* in_sizes, int n_in,
                              void* d_out, int out_size)
{
    const float* x   = (const float*)d_in[0];
    const float* W0  = (const float*)d_in[1];
    const float* U0  = (const float*)d_in[2];
    const float* b0  = (const float*)d_in[3];
    const float* W1  = (const float*)d_in[4];
    const float* U1  = (const float*)d_in[5];
    const float* b1  = (const float*)d_in[6];
    const float* Wfc = (const float*)d_in[7];
    const float* bfc = (const float*)d_in[8];

    cudaFuncSetAttribute(lstm_kernel, cudaFuncAttributeMaxDynamicSharedMemorySize, SMEM_BYTES);
    cudaFuncSetAttribute(precomp_kernel, cudaFuncAttributeMaxDynamicSharedMemorySize, SMEM_BYTES);

    split_x_kernel<<<65536, 256>>>(x);
    pack_w_kernel<<<3584, 256>>>(W0, U0, W1, U1);
    precomp_kernel<<<TSEQ * 128, NTHR, SMEM_BYTES>>>();
    lstm_kernel<<<NCTA, NTHR, SMEM_BYTES>>>(b0, b1);
    out_kernel<<<8, 256>>>(Wfc, bfc, (float*)d_out);
}

// round 15
// speedup vs baseline: 1.0763x; 1.0763x over previous
#include <cuda_runtime.h>
#include <cuda_fp16.h>
#include <cstdint>

// ============================================================================
// 2-layer LSTM (B=256, T=256, IN=256, U=512) + Dense(1).
// R14 = R12 (proven 6686us: x@W0 precomputed, A LDG->reg->STS, B cp.async
// double-buffered) + ONE change: the grid barrier is split into 4 independent
// mb-group barriers (32 CTAs each). The 4 batch-row groups never exchange
// data through the recurrence, so they are provably independent.
// 128 persistent CTAs (4 mb x 32 ub), CTA = 64 batch rows x 16 units.
// fp16 split-2 mma.sync.m16n8k16, fp32 accum (fp32-grade accuracy).
// ============================================================================

#define TSEQ 256
#define NB   256
#define DIN  256
#define NU   512
#define NCTA 128
#define NTHR 256

// A smem geometry (words = uint32 = 2 halves), KC=64, single buffer
#define AROWW 36                    // row stride in words (32 + 4 pad)
#define PLANE (64 * AROWW)          // 2304 words per plane
#define ABYTES (2 * PLANE * 4)      // hi+lo: 18432 B
// B smem: double-buffered 16KB chunks (4 kt x 8 n8 x 32 lanes x 16B)
#define BOFF_W (ABYTES / 4)         // word offset of B region
#define BCHUNKW 4096                // words per B chunk (16KB)
#define SMEM_BYTES (ABYTES + 2 * BCHUNKW * 4)   // 51200 B

// ---- device state ----
__device__ __align__(16) __half g_xh[NB * TSEQ * DIN];
__device__ __align__(16) __half g_xl[NB * TSEQ * DIN];
__device__ __align__(16) __half g_h0h[2][NB][NU];
__device__ __align__(16) __half g_h0l[2][NB][NU];
__device__ __align__(16) __half g_h1h[2][NB][NU];
__device__ __align__(16) __half g_h1l[2][NB][NU];
__device__ unsigned g_bar[1024];    // [mb][t] = [4][256]

// precomputed x@W0, per-thread fragment layout: [t*128+tile][tid][16] f32
__device__ __align__(16) float g_z0x[(size_t)TSEQ * 128 * NTHR * 16];

// packed weight fragments: [ub][kt][n8][lane] -> 16B {b0h,b1h,b0l,b1l}
__device__ __align__(16) uint4 g_W0pk[32 * 16 * 8 * 32];
__device__ __align__(16) uint4 g_U0pk[32 * 32 * 8 * 32];
__device__ __align__(16) uint4 g_W1pk[32 * 32 * 8 * 32];
__device__ __align__(16) uint4 g_U1pk[32 * 32 * 8 * 32];

__device__ __forceinline__ float sigf(float x) { return 1.0f / (1.0f + __expf(-x)); }
__device__ __forceinline__ float tanhfast(float x) { return 2.0f / (1.0f + __expf(-2.0f * x)) - 1.0f; }

#define MMA16816(d, a0, a1, a2, a3, bb0, bb1)                                   \
    asm volatile("mma.sync.aligned.m16n8k16.row.col.f32.f16.f16.f32 "           \
        "{%0,%1,%2,%3}, {%4,%5,%6,%7}, {%8,%9}, {%0,%1,%2,%3};"                 \
        : "+f"((d)[0]), "+f"((d)[1]), "+f"((d)[2]), "+f"((d)[3])                \
        : "r"(a0), "r"(a1), "r"(a2), "r"(a3), "r"(bb0), "r"(bb1))

#define CP16(dst, src) asm volatile("cp.async.cg.shared.global [%0], [%1], 16;" \
        :: "r"(dst), "l"(src))
#define CP_COMMIT()    asm volatile("cp.async.commit_group;" ::: "memory")
#define CP_WAIT(n)     asm volatile("cp.async.wait_group %0;" :: "n"(n) : "memory")

__device__ __forceinline__ uint32_t smem_u32(const void* p) {
    uint32_t a;
    asm("{ .reg .u64 t; cvta.to.shared.u64 t, %1; cvt.u32.u64 %0, t; }" : "=r"(a) : "l"(p));
    return a;
}

// ---------------------------------------------------------------------------
// prep kernels (run every launch; deterministic)
// ---------------------------------------------------------------------------
__global__ void split_x_kernel(const float* __restrict__ x) {
    int i = blockIdx.x * blockDim.x + threadIdx.x;      // 65536 x 256 = 16.7M
    float v = x[i];
    __half hi = __float2half(v);
    g_xh[i] = hi;
    g_xl[i] = __float2half(v - __half2float(hi));
    if (i < 1024) g_bar[i] = 0u;
    if (i < 262144) {
        ((__half*)g_h0h)[i] = __ushort_as_half(0);
        ((__half*)g_h0l)[i] = __ushort_as_half(0);
        ((__half*)g_h1h)[i] = __ushort_as_half(0);
        ((__half*)g_h1l)[i] = __ushort_as_half(0);
    }
}

__device__ __forceinline__ uint32_t pack_hl(float v0, float v1, int lo) {
    __half h0 = __float2half(v0), h1 = __float2half(v1);
    if (lo) {
        h0 = __float2half(v0 - __half2float(h0));
        h1 = __float2half(v1 - __half2float(h1));
    }
    __half2 p = __halves2half2(h0, h1);
    return *(uint32_t*)&p;
}

__global__ void pack_w_kernel(const float* __restrict__ W0, const float* __restrict__ U0,
                              const float* __restrict__ W1, const float* __restrict__ U1) {
    int id = blockIdx.x * blockDim.x + threadIdx.x;     // 3584 x 256 = 917504
    int lane = id & 31;
    int n8   = (id >> 5) & 7;
    int rest = id >> 8;
    int ktg  = rest % 112;
    int ub   = rest / 112;

    const float* M; uint4* dst; int kt;
    if      (ktg < 16) { M = W0; kt = ktg;      dst = g_W0pk + (((ub * 16 + kt) * 8 + n8) * 32 + lane); }
    else if (ktg < 48) { M = U0; kt = ktg - 16; dst = g_U0pk + (((ub * 32 + kt) * 8 + n8) * 32 + lane); }
    else if (ktg < 80) { M = W1; kt = ktg - 48; dst = g_W1pk + (((ub * 32 + kt) * 8 + n8) * 32 + lane); }
    else               { M = U1; kt = ktg - 80; dst = g_U1pk + (((ub * 32 + kt) * 8 + n8) * 32 + lane); }

    int n = n8 * 8 + (lane >> 2);        // local col 0..63, n = f*4 + g
    int f = n >> 2, g = n & 3;
    int col = g * NU + ub * 16 + f;
    int k0 = kt * 16 + (lane & 3) * 2;

    float v00 = M[(size_t)(k0 + 0) * 2048 + col];
    float v01 = M[(size_t)(k0 + 1) * 2048 + col];
    float v10 = M[(size_t)(k0 + 8) * 2048 + col];
    float v11 = M[(size_t)(k0 + 9) * 2048 + col];

    uint4 o;
    o.x = pack_hl(v00, v01, 0);
    o.y = pack_hl(v10, v11, 0);
    o.z = pack_hl(v00, v01, 1);
    o.w = pack_hl(v10, v11, 1);
    *dst = o;
}

// ---------------------------------------------------------------------------
// mb-group barrier: 32 CTAs sharing the same mb (the 4 mb groups never
// exchange data through the recurrence -> fully independent).
__device__ __forceinline__ void gbar(int mb, int slot) {
    __syncthreads();
    if (threadIdx.x == 0) {
        __threadfence();
        unsigned* b = &g_bar[mb * 256 + slot];
        unsigned arr = atomicAdd(b, 1u) + 1u;
        if (arr < 32u) {
            while (*((volatile unsigned*)b) < 32u) __nanosleep(64);
        }
        __threadfence();
    }
    __syncthreads();
}

// A chunk (64 rows x 64 k, hi+lo planes): 1024 uint4 / 256 thr = 4 per thread.
__device__ __forceinline__ void fetchA(const __half* hi, const __half* lo,
                                       int stride, int m0, uint4 ra[4]) {
    int tid = threadIdx.x;
#pragma unroll
    for (int i = 0; i < 4; i++) {
        int idx = i * NTHR + tid;
        int pl = idx >> 9, v = idx & 511;
        int row = v >> 3, q = v & 7;
        const __half* p = (pl ? lo : hi) + (size_t)(m0 + row) * stride + q * 8;
        ra[i] = *(const uint4*)p;
    }
}
__device__ __forceinline__ void storeA(uint32_t* sA, const uint4 ra[4]) {
    int tid = threadIdx.x;
#pragma unroll
    for (int i = 0; i < 4; i++) {
        int idx = i * NTHR + tid;
        int pl = idx >> 9, v = idx & 511;
        int row = v >> 3, q = v & 7;
        *(uint4*)(sA + pl * PLANE + row * AROWW + q * 4) = ra[i];
    }
}

// B chunk: contiguous 1024 uint4 (16KB) from packed weights -> smem slot.
__device__ __forceinline__ void issueB(uint32_t dstb, const uint4* src) {
    int tid = threadIdx.x;
#pragma unroll
    for (int i = 0; i < 4; i++) {
        int idx = i * NTHR + tid;
        CP16(dstb + idx * 16, (const void*)(src + idx));
    }
    CP_COMMIT();
}

// one layer: nchunks K-chunks of 64. A: LDG->reg->STS (single buffer).
// B: cp.async one chunk ahead, double-buffered smem. acc[4][4] per warp.
// zinit: optional per-thread fragment-layout initial accumulator (else 0).
__device__ __forceinline__ void run_layer(
    uint32_t* sbuf, uint32_t sbase,
    int nchunks, int splitc,
    const __half* a1h, const __half* a1l, int str1,
    const __half* a2h, const __half* a2l,
    const uint4* pkA, int ktA, const uint4* pkB,
    int m0, int ub, float acc[4][4], const float4* zinit)
{
    int tid = threadIdx.x, lane = tid & 31, w = tid >> 5;
    int warpM = w & 3, nh = w >> 2;

    if (zinit) {
#pragma unroll
        for (int nt = 0; nt < 4; nt++) {
            float4 v = zinit[nt];
            acc[nt][0] = v.x; acc[nt][1] = v.y; acc[nt][2] = v.z; acc[nt][3] = v.w;
        }
    } else {
#pragma unroll
        for (int nt = 0; nt < 4; nt++)
#pragma unroll
            for (int r = 0; r < 4; r++) acc[nt][r] = 0.f;
    }

    uint4 ra[4];
    fetchA(a1h, a1l, str1, m0, ra);

    // prime B chunk 0
    issueB(sbase + BOFF_W * 4, pkA + (size_t)(ub * ktA) * 256);

#pragma unroll 1
    for (int c = 0; c < nchunks; c++) {
        if (c + 1 < nchunks) {
            int cn = c + 1;
            const uint4* src = (cn < splitc)
                ? pkA + (size_t)(ub * ktA + cn * 4) * 256
                : pkB + (size_t)(ub * 32 + (cn - splitc) * 4) * 256;
            issueB(sbase + (BOFF_W + (cn & 1) * BCHUNKW) * 4, src);
        }
        storeA(sbuf, ra);
        if (c + 1 < nchunks) CP_WAIT(1); else CP_WAIT(0);
        __syncthreads();
        if (c + 1 < nchunks) {
            int cn = c + 1;
            if (cn < splitc) fetchA(a1h + cn * 64, a1l + cn * 64, str1, m0, ra);
            else             fetchA(a2h + (cn - splitc) * 64, a2l + (cn - splitc) * 64, NU, m0, ra);
        }
        uint32_t* sAh = sbuf;
        uint32_t* sAl = sbuf + PLANE;
        const uint4* sBv = (const uint4*)(sbuf + BOFF_W + (c & 1) * BCHUNKW);
#pragma unroll
        for (int j = 0; j < 4; j++) {
            const uint4* bq = sBv + ((j * 8 + nh * 4) * 32 + lane);
            uint4 f0 = bq[0];
            uint4 f1 = bq[32];
            uint4 f2 = bq[64];
            uint4 f3 = bq[96];

            int ab = (warpM * 16 + (lane >> 2)) * AROWW + j * 8 + (lane & 3);
            uint32_t ah0 = sAh[ab],       ah1 = sAh[ab + 8 * AROWW];
            uint32_t ah2 = sAh[ab + 4],   ah3 = sAh[ab + 8 * AROWW + 4];
            uint32_t al0 = sAl[ab],       al1 = sAl[ab + 8 * AROWW];
            uint32_t al2 = sAl[ab + 4],   al3 = sAl[ab + 8 * AROWW + 4];

            MMA16816(acc[0], ah0, ah1, ah2, ah3, f0.x, f0.y);
            MMA16816(acc[1], ah0, ah1, ah2, ah3, f1.x, f1.y);
            MMA16816(acc[2], ah0, ah1, ah2, ah3, f2.x, f2.y);
            MMA16816(acc[3], ah0, ah1, ah2, ah3, f3.x, f3.y);
            MMA16816(acc[0], ah0, ah1, ah2, ah3, f0.z, f0.w);
            MMA16816(acc[1], ah0, ah1, ah2, ah3, f1.z, f1.w);
            MMA16816(acc[2], ah0, ah1, ah2, ah3, f2.z, f2.w);
            MMA16816(acc[3], ah0, ah1, ah2, ah3, f3.z, f3.w);
            MMA16816(acc[0], al0, al1, al2, al3, f0.x, f0.y);
            MMA16816(acc[1], al0, al1, al2, al3, f1.x, f1.y);
            MMA16816(acc[2], al0, al1, al2, al3, f2.x, f2.y);
            MMA16816(acc[3], al0, al1, al2, al3, f3.x, f3.y);
        }
        __syncthreads();
    }
}

// ---------------------------------------------------------------------------
// precompute z0x = x @ W0 (no bias), all timesteps in parallel.
__global__ void __launch_bounds__(NTHR, 1) precomp_kernel() {
    extern __shared__ __align__(16) uint32_t sbuf[];
    int bid = blockIdx.x;
    int t = bid >> 7;
    int bx = bid & 127;
    int ub = bx & 31, mb = bx >> 5;
    int m0 = mb * 64;
    uint32_t sbase = smem_u32(sbuf);

    float acc[4][4];
    run_layer(sbuf, sbase, 4, 4,
              g_xh + t * DIN, g_xl + t * DIN, TSEQ * DIN,
              (const __half*)0, (const __half*)0,
              g_W0pk, 16, g_W0pk,
              m0, ub, acc, (const float4*)0);

    float4* dst = (float4*)&g_z0x[(((size_t)bid) * NTHR + threadIdx.x) * 16];
#pragma unroll
    for (int nt = 0; nt < 4; nt++)
        dst[nt] = make_float4(acc[nt][0], acc[nt][1], acc[nt][2], acc[nt][3]);
}

// epilogue: gate exchange via shfl_xor(1), cell update, write h hi/lo planes.
__device__ __forceinline__ void epilogue(float acc[4][4], float cst[4],
                                         const float* sb,
                                         __half* dsth, __half* dstl,
                                         int m0, int u0)
{
    int tid = threadIdx.x, lane = tid & 31, w = tid >> 5;
    int warpM = w & 3, nh = w >> 2;
    int gp = lane & 1;
    int rlow = m0 + warpM * 16 + (lane >> 2);
#pragma unroll
    for (int nt = 0; nt < 4; nt++) {
        float c0 = acc[nt][0], c1 = acc[nt][1], c2 = acc[nt][2], c3 = acc[nt][3];
        float e0 = __shfl_xor_sync(0xffffffffu, c0, 1);
        float e1 = __shfl_xor_sync(0xffffffffu, c1, 1);
        float e2 = __shfl_xor_sync(0xffffffffu, c2, 1);
        float e3 = __shfl_xor_sync(0xffffffffu, c3, 1);
        float zi, zf, zg, zo; int row;
        if (!gp) { zi = c0; zf = c1; zg = e0; zo = e1; row = rlow; }
        else     { zi = e2; zf = e3; zg = c2; zo = c3; row = rlow + 8; }
        int ul = nh * 8 + nt * 2 + ((lane >> 1) & 1);
        zi += sb[ul * 4 + 0]; zf += sb[ul * 4 + 1];
        zg += sb[ul * 4 + 2]; zo += sb[ul * 4 + 3];
        float cn = sigf(zf) * cst[nt] + sigf(zi) * tanhfast(zg);
        cst[nt] = cn;
        float h = sigf(zo) * tanhfast(cn);
        __half hh = __float2half(h);
        __half hl = __float2half(h - __half2float(hh));
        dsth[(size_t)row * NU + u0 + ul] = hh;
        dstl[(size_t)row * NU + u0 + ul] = hl;
    }
}

// ---------------------------------------------------------------------------
__global__ void __launch_bounds__(NTHR, 1) lstm_kernel(
    const float* __restrict__ b0, const float* __restrict__ b1)
{
    extern __shared__ __align__(16) uint32_t sbuf[];   // A 18432B | B 2x16KB
    __shared__ float sb0[64], sb1[64];

    int tid = threadIdx.x;
    int bx = blockIdx.x;
    int ub = bx & 31, mb = bx >> 5;
    int u0 = ub * 16, m0 = mb * 64;
    uint32_t sbase = smem_u32(sbuf);

    if (tid < 64) {
        int f = tid >> 2, g = tid & 3;
        sb0[tid] = b0[g * NU + u0 + f];
        sb1[tid] = b1[g * NU + u0 + f];
    }
    __syncthreads();

    float cst0[4] = {0.f, 0.f, 0.f, 0.f};
    float cst1[4] = {0.f, 0.f, 0.f, 0.f};
    float acc[4][4];

#pragma unroll 1
    for (int t = 0; t < TSEQ; t++) {
        int p = t & 1;
        const __half* h0ch = &g_h0h[p][0][0];     const __half* h0cl = &g_h0l[p][0][0];
        __half*       h0nh = &g_h0h[p ^ 1][0][0]; __half*       h0nl = &g_h0l[p ^ 1][0][0];
        const __half* h1ch = &g_h1h[p][0][0];     const __half* h1cl = &g_h1l[p][0][0];
        __half*       h1nh = &g_h1h[p ^ 1][0][0]; __half*       h1nl = &g_h1l[p ^ 1][0][0];

        // layer 0: acc init = z0x(t) fragments; A = h0c (8 chunks), B = U0pk
        const float4* zi = (const float4*)
            &g_z0x[(((size_t)(t * 128 + bx)) * NTHR + tid) * 16];
        run_layer(sbuf, sbase, 8, 8,
                  h0ch, h0cl, NU,
                  (const __half*)0, (const __half*)0,
                  g_U0pk, 32, g_U0pk,
                  m0, ub, acc, zi);
        epilogue(acc, cst0, sb0, h0nh, h0nl, m0, u0);
        gbar(mb, t);    // 32-CTA mb-group barrier (groups independent)

        // layer 1: A = [h0n (8 chunks) | h1c (8 chunks)], B = [W1pk ; U1pk]
        run_layer(sbuf, sbase, 16, 8,
                  h0nh, h0nl, NU,
                  h1ch, h1cl,
                  g_W1pk, 32, g_U1pk,
                  m0, ub, acc, (const float4*)0);
        epilogue(acc, cst1, sb1, h1nh, h1nl, m0, u0);
    }
}

// Final head: out[b] = h1_final[b,:] @ Wfc + bfc. Final h1 is in plane buffer 0.
__global__ void out_kernel(const float* __restrict__ Wfc,
                           const float* __restrict__ bfc,
                           float* __restrict__ out)
{
    int warp = threadIdx.x >> 5, lane = threadIdx.x & 31;
    int wglob = blockIdx.x * 8 + warp;
#pragma unroll
    for (int i = 0; i < 4; i++) {
        int b = wglob * 4 + i;
        float s = 0.f;
        for (int u = lane; u < NU; u += 32) {
            float h = __half2float(g_h1h[0][b][u]) + __half2float(g_h1l[0][b][u]);
            s += h * Wfc[u];
        }
#pragma unroll
        for (int off = 16; off; off >>= 1) s += __shfl_down_sync(0xffffffffu, s, off);
        if (lane == 0) out[b] = s + bfc[0];
    }
}

extern "C" void kernel_launch(void* const* d_in, const int* in_sizes, int n_in,
                              void* d_out, int out_size)
{
    const float* x   = (const float*)d_in[0];
    const float* W0  = (const float*)d_in[1];
    const float* U0  = (const float*)d_in[2];
    const float* b0  = (const float*)d_in[3];
    const float* W1  = (const float*)d_in[4];
    const float* U1  = (const float*)d_in[5];
    const float* b1  = (const float*)d_in[6];
    const float* Wfc = (const float*)d_in[7];
    const float* bfc = (const float*)d_in[8];

    cudaFuncSetAttribute(lstm_kernel, cudaFuncAttributeMaxDynamicSharedMemorySize, SMEM_BYTES);
    cudaFuncSetAttribute(precomp_kernel, cudaFuncAttributeMaxDynamicSharedMemorySize, SMEM_BYTES);

    split_x_kernel<<<65536, 256>>>(x);
    pack_w_kernel<<<3584, 256>>>(W0, U0, W1, U1);
    precomp_kernel<<<TSEQ * 128, NTHR, SMEM_BYTES>>>();
    lstm_kernel<<<NCTA, NTHR, SMEM_BYTES>>>(b0, b1);
    out_kernel<<<8, 256>>>(Wfc, bfc, (float*)d_out);
}